// round 6
// baseline (speedup 1.0000x reference)
#include <cuda_runtime.h>
#include <cuda_fp16.h>
#include <float.h>
#include <math.h>
#include <cstdint>

#define BB 8
#define NN 2048
#define DD 512

// ---------------------------------------------------------------------------
// Scratch (__device__ globals only — allocation-free contract)
// ---------------------------------------------------------------------------
__device__ float g_xx[BB * NN];
__device__ float g_dist[(size_t)BB * NN * NN];          // 134 MB
__device__ __half g_sp[2][(size_t)BB * NN * DD];        // h / l fp16 splits, 32 MB

__device__ __forceinline__ uint32_t smem_u32(const void* p) {
    uint32_t a;
    asm("{ .reg .u64 t; cvta.to.shared.u64 t, %1; cvt.u32.u64 %0, t; }" : "=r"(a) : "l"(p));
    return a;
}

#define LDSM4(r0, r1, r2, r3, addr) \
    asm volatile("ldmatrix.sync.aligned.m8n8.x4.shared.b16 {%0,%1,%2,%3}, [%4];" \
                 : "=r"(r0), "=r"(r1), "=r"(r2), "=r"(r3) : "r"(addr))

#define MMA16816(c, a, b0, b1) \
    asm volatile("mma.sync.aligned.m16n8k16.row.col.f32.f16.f16.f32 " \
                 "{%0,%1,%2,%3}, {%4,%5,%6,%7}, {%8,%9}, {%0,%1,%2,%3};" \
                 : "+f"((c)[0]), "+f"((c)[1]), "+f"((c)[2]), "+f"((c)[3]) \
                 : "r"((a)[0]), "r"((a)[1]), "r"((a)[2]), "r"((a)[3]), "r"(b0), "r"(b1))

#define CP_ASYNC16(dst, src) \
    asm volatile("cp.async.cg.shared.global [%0], [%1], 16;" :: "r"(dst), "l"(src))
#define CP_COMMIT() asm volatile("cp.async.commit_group;" ::: "memory")

// ---------------------------------------------------------------------------
// Kernel 0: fp16 2-word split of put  (x = h + l exactly to 2^-22)
// ---------------------------------------------------------------------------
__global__ __launch_bounds__(256) void split_kernel(const float* __restrict__ put) {
    size_t i4 = ((size_t)blockIdx.x * 256 + threadIdx.x) * 4;
    float4 v = *(const float4*)(put + i4);
    float x[4] = {v.x, v.y, v.z, v.w};
    __half h[4], l[4];
#pragma unroll
    for (int q = 0; q < 4; q++) {
        h[q] = __float2half(x[q]);
        l[q] = __float2half(x[q] - __half2float(h[q]));
    }
    *(uint2*)(&g_sp[0][i4]) = *(uint2*)h;
    *(uint2*)(&g_sp[1][i4]) = *(uint2*)l;
}

// ---------------------------------------------------------------------------
// Kernel 1: row squared norms (fp32 exact)
// ---------------------------------------------------------------------------
__global__ __launch_bounds__(256) void xx_kernel(const float* __restrict__ put) {
    int row  = blockIdx.x * 8 + (threadIdx.x >> 5);
    int lane = threadIdx.x & 31;
    const float* p = put + (size_t)row * DD;
    float s = 0.f;
#pragma unroll
    for (int f = 0; f < 4; f++) {
        float4 v = *(const float4*)(p + f * 128 + lane * 4);
        s = fmaf(v.x, v.x, s); s = fmaf(v.y, v.y, s);
        s = fmaf(v.z, v.z, s); s = fmaf(v.w, v.w, s);
    }
#pragma unroll
    for (int off = 16; off; off >>= 1) s += __shfl_xor_sync(0xffffffffu, s, off);
    if (lane == 0) g_xx[row] = s;
}

// ---------------------------------------------------------------------------
// Kernel 2: distance tiles (unchanged R4/R5 core), now per-batch launch.
// ---------------------------------------------------------------------------
#define PITCH_H 40
#define TILE_B  (128 * PITCH_H * 2)
#define BUF_B   (4 * TILE_B)
#define XX_OFF  (2 * BUF_B)
#define SM_TOTAL (XX_OFF + 1024)
#define T_PITCH 136

__global__ __launch_bounds__(256, 1) void dist_mma_kernel(int b) {
    int bx = blockIdx.x, by = blockIdx.y;
    if (by > bx) return;
    bool diag = (bx == by);

    extern __shared__ char smem[];
    uint32_t sbase = smem_u32(smem);
    int tid  = threadIdx.x;
    int lane = tid & 31;
    int wid  = tid >> 5;

    int j0 = by * 128, i0 = bx * 128, bofs = b * NN;

    float* xxA = (float*)(smem + XX_OFF);
    float* xxB = (float*)(smem + XX_OFF + 512);
    if (tid < 128) {
        xxA[tid] = g_xx[bofs + j0 + tid];
        xxB[tid] = g_xx[bofs + i0 + tid];
    }

    int fr   = (tid >> 2);
    int fck  = tid & 3;
    auto fill = [&](int buf, int kt) {
#pragma unroll
        for (int q = 0; q < 8; q++) {
            int rr   = fr + 64 * (q & 1);
            int tile = q >> 1;
            int word = tile & 1;
            int grow = (tile < 2 ? j0 : i0) + rr;
            const __half* src = &g_sp[word][(size_t)(bofs + grow) * DD + kt * 32 + fck * 8];
            uint32_t dst = sbase + buf * BUF_B + tile * TILE_B + rr * (PITCH_H * 2) + fck * 16;
            CP_ASYNC16(dst, src);
        }
    };

    int wm = (wid >> 2) * 64;
    int wn = (wid & 3) * 32;

    float acc[4][4][4];
#pragma unroll
    for (int im = 0; im < 4; im++)
#pragma unroll
        for (int in = 0; in < 4; in++)
#pragma unroll
            for (int q = 0; q < 4; q++) acc[im][in][q] = 0.f;

    fill(0, 0);
    CP_COMMIT();

    int arow = lane & 15;
    int acol = (lane >> 4) * 8;
    int brow = (lane & 7) + ((lane >> 4) << 3);
    int bcol = ((lane >> 3) & 1) * 8;

    for (int kt = 0; kt < 16; kt++) {
        if (kt < 15) { fill((kt + 1) & 1, kt + 1); CP_COMMIT(); }
        if (kt < 15) asm volatile("cp.async.wait_group 1;" ::: "memory");
        else         asm volatile("cp.async.wait_group 0;" ::: "memory");
        __syncthreads();

        uint32_t base = sbase + (kt & 1) * BUF_B;
#pragma unroll
        for (int kc = 0; kc < 2; kc++) {
            int kofs = kc * 16;
            uint32_t ah[4][4], al[4][4];
#pragma unroll
            for (int im = 0; im < 4; im++) {
                uint32_t off = (uint32_t)((wm + im * 16 + arow) * (PITCH_H * 2) + (kofs + acol) * 2);
                LDSM4(ah[im][0], ah[im][1], ah[im][2], ah[im][3], base + 0 * TILE_B + off);
                LDSM4(al[im][0], al[im][1], al[im][2], al[im][3], base + 1 * TILE_B + off);
            }
            uint32_t bh[8], bl[8];
#pragma unroll
            for (int bp = 0; bp < 2; bp++) {
                uint32_t off = (uint32_t)((wn + bp * 16 + brow) * (PITCH_H * 2) + (kofs + bcol) * 2);
                LDSM4(bh[bp*4+0], bh[bp*4+1], bh[bp*4+2], bh[bp*4+3], base + 2 * TILE_B + off);
                LDSM4(bl[bp*4+0], bl[bp*4+1], bl[bp*4+2], bl[bp*4+3], base + 3 * TILE_B + off);
            }
#pragma unroll
            for (int im = 0; im < 4; im++)
#pragma unroll
                for (int in = 0; in < 4; in++) {
                    MMA16816(acc[im][in], ah[im], bh[in*2], bh[in*2+1]);
                    MMA16816(acc[im][in], ah[im], bl[in*2], bl[in*2+1]);
                    MMA16816(acc[im][in], al[im], bh[in*2], bh[in*2+1]);
                }
        }
        __syncthreads();
    }

    float* smemT = (float*)smem;

#pragma unroll
    for (int im = 0; im < 4; im++) {
#pragma unroll
        for (int h2 = 0; h2 < 2; h2++) {
            int row = wm + im * 16 + (lane >> 2) + h2 * 8;
            float xj = xxA[row];
#pragma unroll
            for (int in = 0; in < 4; in++) {
                int n = wn + in * 8 + (lane & 3) * 2;
                float g0 = acc[im][in][h2 * 2 + 0];
                float g1 = acc[im][in][h2 * 2 + 1];
                float v0 = sqrtf(fmaxf((xj + xxB[n])     - 2.0f * g0, 0.0f));
                float v1 = sqrtf(fmaxf((xj + xxB[n + 1]) - 2.0f * g1, 0.0f));
                *(float2*)&g_dist[((size_t)(bofs + j0 + row)) * NN + i0 + n] = make_float2(v0, v1);
                if (!diag) {
                    smemT[(n)     * T_PITCH + row] = v0;
                    smemT[(n + 1) * T_PITCH + row] = v1;
                }
            }
        }
    }

    if (!diag) {
        __syncthreads();
#pragma unroll
        for (int q = 0; q < 16; q++) {
            int fid = tid + 256 * q;
            int nrow = fid >> 5, f4 = fid & 31;
            float4 val = *(float4*)&smemT[nrow * T_PITCH + f4 * 4];
            *(float4*)&g_dist[((size_t)(bofs + i0 + nrow)) * NN + j0 + f4 * 4] = val;
        }
    }
}

// ---------------------------------------------------------------------------
// Kernel 3: top-16 radix select, 4 rows per block, phase-parallel scans.
// ---------------------------------------------------------------------------
#define CAND_CAP 512
// dynamic smem layout (uint32 words):
//   rows   [4][2048]      off 0
//   hist   [4][256]       off 8192
//   cand_v [4][CAND_CAP]  off 9216
//   cand_i [4][CAND_CAP]  off 11264
//   sure   [4][16]        off 13312
//   widx   [4][16]        off 13376
//   scal   b0/c0/P/clt/nsure/ncand [4] each, off 13440
#define TK_ROWS   0
#define TK_HIST   8192
#define TK_CANDV  9216
#define TK_CANDI  (TK_CANDV + 4 * CAND_CAP)
#define TK_SURE   (TK_CANDI + 4 * CAND_CAP)
#define TK_WIDX   (TK_SURE + 64)
#define TK_SCAL   (TK_WIDX + 64)
#define TK_SMEM_BYTES ((TK_SCAL + 32) * 4)

__device__ __forceinline__ void cmin3(uint32_t& v, uint32_t& i, uint32_t& j,
                                      uint32_t v2, uint32_t i2, uint32_t j2) {
    if (v2 < v || (v2 == v && i2 < i)) { v = v2; i = i2; j = j2; }
}

__global__ __launch_bounds__(256) void topk4_kernel(float* __restrict__ out, int batch) {
    extern __shared__ uint32_t sh[];
    uint32_t* rows   = sh + TK_ROWS;
    uint32_t* hist   = sh + TK_HIST;
    uint32_t* candv  = sh + TK_CANDV;
    uint32_t* candi  = sh + TK_CANDI;
    uint32_t* sure   = sh + TK_SURE;
    uint32_t* widx   = sh + TK_WIDX;
    uint32_t* s_b0   = sh + TK_SCAL;       // [4]
    uint32_t* s_c0   = sh + TK_SCAL + 4;
    uint32_t* s_P    = sh + TK_SCAL + 8;
    uint32_t* s_clt  = sh + TK_SCAL + 12;
    uint32_t* s_nsr  = sh + TK_SCAL + 16;
    uint32_t* s_ncd  = sh + TK_SCAL + 20;

    int tid  = threadIdx.x;
    int lane = tid & 31;
    int wid  = tid >> 5;
    size_t row0 = (size_t)batch * NN + (size_t)blockIdx.x * 4;

    // ---- load 4 contiguous rows (32 KB) ----
    const uint4* src = (const uint4*)(g_dist + row0 * NN);
#pragma unroll
    for (int q = 0; q < 8; q++)
        ((uint4*)rows)[tid + 256 * q] = src[tid + 256 * q];

    // zero hist + counters
#pragma unroll
    for (int q = 0; q < 4; q++) hist[tid + 256 * q] = 0;
    if (tid < 4) { s_nsr[tid] = 0; s_ncd[tid] = 0; }
    __syncthreads();

    // ---- level 0 hist: bits [31:24], warp-aggregated ----
#pragma unroll
    for (int r = 0; r < 4; r++) {
        const uint32_t* rw = rows + r * NN + tid * 8;
#pragma unroll
        for (int q = 0; q < 8; q++) {
            uint32_t bin = rw[q] >> 24;
            uint32_t mask = __match_any_sync(0xffffffffu, bin);
            if (lane == (__ffs(mask) - 1)) atomicAdd(&hist[r * 256 + bin], __popc(mask));
        }
    }
    __syncthreads();

    // ---- scan: warp r finds level-0 bin of the 16th smallest ----
    if (wid < 4) {
        int r = wid;
        uint32_t loc[8], s = 0;
#pragma unroll
        for (int i = 0; i < 8; i++) { loc[i] = hist[r * 256 + lane * 8 + i]; s += loc[i]; }
        uint32_t incl = s;
#pragma unroll
        for (int off = 1; off < 32; off <<= 1) {
            uint32_t t2 = __shfl_up_sync(0xffffffffu, incl, off);
            if (lane >= off) incl += t2;
        }
        uint32_t run = incl - s;
#pragma unroll
        for (int i = 0; i < 8; i++) {
            if (run < 16u && 16u <= run + loc[i]) { s_b0[r] = lane * 8 + i; s_c0[r] = run; }
            run += loc[i];
        }
    }
    __syncthreads();

    uint32_t b0r[4];
#pragma unroll
    for (int r = 0; r < 4; r++) b0r[r] = s_b0[r];

    // re-zero hist
#pragma unroll
    for (int q = 0; q < 4; q++) hist[tid + 256 * q] = 0;
    __syncthreads();

    // ---- level 1 hist: bits [23:16] where top byte == b0 ----
#pragma unroll
    for (int r = 0; r < 4; r++) {
        const uint32_t* rw = rows + r * NN + tid * 8;
        uint32_t b0 = b0r[r];
#pragma unroll
        for (int q = 0; q < 8; q++) {
            uint32_t v = rw[q];
            bool act = ((v >> 24) == b0);
            uint32_t bin = act ? ((v >> 16) & 255u) : (256u + lane);
            uint32_t mask = __match_any_sync(0xffffffffu, bin);
            if (act && lane == (__ffs(mask) - 1)) atomicAdd(&hist[r * 256 + bin], __popc(mask));
        }
    }
    __syncthreads();

    // ---- scan: warp r finds level-1 prefix P[r] ----
    if (wid < 4) {
        int r = wid;
        uint32_t k1 = 16u - s_c0[r];
        uint32_t loc[8], s = 0;
#pragma unroll
        for (int i = 0; i < 8; i++) { loc[i] = hist[r * 256 + lane * 8 + i]; s += loc[i]; }
        uint32_t incl = s;
#pragma unroll
        for (int off = 1; off < 32; off <<= 1) {
            uint32_t t2 = __shfl_up_sync(0xffffffffu, incl, off);
            if (lane >= off) incl += t2;
        }
        uint32_t run = incl - s;
#pragma unroll
        for (int i = 0; i < 8; i++) {
            if (run < k1 && k1 <= run + loc[i]) {
                s_P[r]   = (s_b0[r] << 8) | (uint32_t)(lane * 8 + i);
                s_clt[r] = s_c0[r] + run;
            }
            run += loc[i];
        }
    }
    __syncthreads();

    // ---- gather sure / candidate per row ----
#pragma unroll
    for (int r = 0; r < 4; r++) {
        uint32_t P = s_P[r];
        const uint32_t* rw = rows + r * NN + tid * 8;
#pragma unroll
        for (int q = 0; q < 8; q++) {
            uint32_t v = rw[q];
            uint32_t hi = v >> 16;
            if (hi < P) {
                uint32_t p = atomicAdd(&s_nsr[r], 1u);
                sure[r * 16 + p] = tid * 8 + q;
            } else if (hi == P) {
                uint32_t p = atomicAdd(&s_ncd[r], 1u);
                if (p < CAND_CAP) {
                    candv[r * CAND_CAP + p] = v;
                    candi[r * CAND_CAP + p] = tid * 8 + q;
                }
            }
        }
    }
    __syncthreads();

    // ---- warp r: stable-min rounds over its candidate list ----
    if (wid < 4) {
        int r = wid;
        uint32_t m = 16u - s_clt[r];
        uint32_t n = min(s_ncd[r], (uint32_t)CAND_CAP);
        uint32_t* cv = candv + r * CAND_CAP;
        uint32_t* ci = candi + r * CAND_CAP;
        for (uint32_t it = 0; it < m; it++) {
            uint32_t bv = 0xffffffffu, bi = 0xffffffffu, bj = 0xffffffffu;
            for (uint32_t j = lane; j < n; j += 32)
                cmin3(bv, bi, bj, cv[j], ci[j], j);
#pragma unroll
            for (int off = 16; off; off >>= 1) {
                uint32_t ov = __shfl_down_sync(0xffffffffu, bv, off);
                uint32_t oi = __shfl_down_sync(0xffffffffu, bi, off);
                uint32_t oj = __shfl_down_sync(0xffffffffu, bj, off);
                cmin3(bv, bi, bj, ov, oi, oj);
            }
            if (lane == 0) {
                widx[r * 16 + it] = bi;
                cv[bj] = 0xffffffffu;
                ci[bj] = 0xffffffffu;
            }
            __syncwarp();
        }
    }
    __syncthreads();

    // ---- write: zero 4 rows, then scatter ones (warp r handles row r) ----
    float* orow0 = out + row0 * NN;
    float4 z = make_float4(0.f, 0.f, 0.f, 0.f);
#pragma unroll
    for (int q = 0; q < 8; q++)
        ((float4*)orow0)[tid + 256 * q] = z;
    __syncthreads();
    if (wid < 4) {
        int r = wid;
        uint32_t clt = s_clt[r], m = 16u - clt;
        float* orow = orow0 + (size_t)r * NN;
        if (lane < clt)                   orow[sure[r * 16 + lane]] = 1.0f;
        if (lane >= 16 && lane < 16 + m)  orow[widx[r * 16 + lane - 16]] = 1.0f;
    }
}

// ---------------------------------------------------------------------------
extern "C" void kernel_launch(void* const* d_in, const int* in_sizes, int n_in,
                              void* d_out, int out_size) {
    const float* put = (const float*)d_in[0];
    float* out = (float*)d_out;

    cudaFuncSetAttribute(dist_mma_kernel, cudaFuncAttributeMaxDynamicSharedMemorySize, SM_TOTAL);
    cudaFuncSetAttribute(topk4_kernel, cudaFuncAttributeMaxDynamicSharedMemorySize, TK_SMEM_BYTES);

    // fork/join side stream (fresh each call; never destroyed — capture-safe)
    cudaStream_t s1;
    cudaStreamCreateWithFlags(&s1, cudaStreamNonBlocking);
    cudaEvent_t evD[BB], evT[BB];
    for (int b = 0; b < BB; b++) {
        cudaEventCreateWithFlags(&evD[b], cudaEventDisableTiming);
        cudaEventCreateWithFlags(&evT[b], cudaEventDisableTiming);
    }

    split_kernel<<<(BB * NN * DD) / (256 * 4), 256>>>(put);
    xx_kernel<<<(BB * NN) / 8, 256>>>(put);

    for (int b = 0; b < BB; b++) {
        dist_mma_kernel<<<dim3(16, 16), 256, SM_TOTAL>>>(b);
        cudaEventRecord(evD[b], 0);
        cudaStreamWaitEvent(s1, evD[b], 0);
        topk4_kernel<<<NN / 4, 256, TK_SMEM_BYTES, s1>>>(out, b);
        cudaEventRecord(evT[b], s1);
    }
    for (int b = 0; b < BB; b++) cudaStreamWaitEvent(0, evT[b], 0);
}

// round 7
// speedup vs baseline: 1.2153x; 1.2153x over previous
#include <cuda_runtime.h>
#include <cuda_fp16.h>
#include <float.h>
#include <math.h>
#include <cstdint>

#define BB 8
#define NN 2048
#define DD 512

// ---------------------------------------------------------------------------
// Scratch (__device__ globals only — allocation-free contract)
// ---------------------------------------------------------------------------
__device__ float g_xx[BB * NN];
__device__ float g_dist[(size_t)BB * NN * NN];          // 134 MB
__device__ __half g_sp[2][(size_t)BB * NN * DD];        // h / l fp16 splits, 32 MB

__device__ __forceinline__ uint32_t smem_u32(const void* p) {
    uint32_t a;
    asm("{ .reg .u64 t; cvta.to.shared.u64 t, %1; cvt.u32.u64 %0, t; }" : "=r"(a) : "l"(p));
    return a;
}

#define LDSM4(r0, r1, r2, r3, addr) \
    asm volatile("ldmatrix.sync.aligned.m8n8.x4.shared.b16 {%0,%1,%2,%3}, [%4];" \
                 : "=r"(r0), "=r"(r1), "=r"(r2), "=r"(r3) : "r"(addr))

#define MMA16816(c, a, b0, b1) \
    asm volatile("mma.sync.aligned.m16n8k16.row.col.f32.f16.f16.f32 " \
                 "{%0,%1,%2,%3}, {%4,%5,%6,%7}, {%8,%9}, {%0,%1,%2,%3};" \
                 : "+f"((c)[0]), "+f"((c)[1]), "+f"((c)[2]), "+f"((c)[3]) \
                 : "r"((a)[0]), "r"((a)[1]), "r"((a)[2]), "r"((a)[3]), "r"(b0), "r"(b1))

#define CP_ASYNC16(dst, src) \
    asm volatile("cp.async.cg.shared.global [%0], [%1], 16;" :: "r"(dst), "l"(src))
#define CP_COMMIT() asm volatile("cp.async.commit_group;" ::: "memory")

// ---------------------------------------------------------------------------
// Kernel 0: fp16 2-word split of put  (x = h + l exactly to 2^-22)
// ---------------------------------------------------------------------------
__global__ __launch_bounds__(256) void split_kernel(const float* __restrict__ put) {
    size_t i4 = ((size_t)blockIdx.x * 256 + threadIdx.x) * 4;
    float4 v = *(const float4*)(put + i4);
    float x[4] = {v.x, v.y, v.z, v.w};
    __half h[4], l[4];
#pragma unroll
    for (int q = 0; q < 4; q++) {
        h[q] = __float2half(x[q]);
        l[q] = __float2half(x[q] - __half2float(h[q]));
    }
    *(uint2*)(&g_sp[0][i4]) = *(uint2*)h;
    *(uint2*)(&g_sp[1][i4]) = *(uint2*)l;
}

// ---------------------------------------------------------------------------
// Kernel 1: row squared norms (fp32 exact)
// ---------------------------------------------------------------------------
__global__ __launch_bounds__(256) void xx_kernel(const float* __restrict__ put) {
    int row  = blockIdx.x * 8 + (threadIdx.x >> 5);
    int lane = threadIdx.x & 31;
    const float* p = put + (size_t)row * DD;
    float s = 0.f;
#pragma unroll
    for (int f = 0; f < 4; f++) {
        float4 v = *(const float4*)(p + f * 128 + lane * 4);
        s = fmaf(v.x, v.x, s); s = fmaf(v.y, v.y, s);
        s = fmaf(v.z, v.z, s); s = fmaf(v.w, v.w, s);
    }
#pragma unroll
    for (int off = 16; off; off >>= 1) s += __shfl_xor_sync(0xffffffffu, s, off);
    if (lane == 0) g_xx[row] = s;
}

// ---------------------------------------------------------------------------
// Kernel 2: distance tiles — single launch over all batches (grid 16,16,8).
// ---------------------------------------------------------------------------
#define PITCH_H 40
#define TILE_B  (128 * PITCH_H * 2)
#define BUF_B   (4 * TILE_B)
#define XX_OFF  (2 * BUF_B)
#define SM_TOTAL (XX_OFF + 1024)
#define T_PITCH 136

__global__ __launch_bounds__(256, 1) void dist_mma_kernel() {
    int bx = blockIdx.x, by = blockIdx.y, b = blockIdx.z;
    if (by > bx) return;
    bool diag = (bx == by);

    extern __shared__ char smem[];
    uint32_t sbase = smem_u32(smem);
    int tid  = threadIdx.x;
    int lane = tid & 31;
    int wid  = tid >> 5;

    int j0 = by * 128, i0 = bx * 128, bofs = b * NN;

    float* xxA = (float*)(smem + XX_OFF);
    float* xxB = (float*)(smem + XX_OFF + 512);
    if (tid < 128) {
        xxA[tid] = g_xx[bofs + j0 + tid];
        xxB[tid] = g_xx[bofs + i0 + tid];
    }

    int fr   = (tid >> 2);
    int fck  = tid & 3;
    auto fill = [&](int buf, int kt) {
#pragma unroll
        for (int q = 0; q < 8; q++) {
            int rr   = fr + 64 * (q & 1);
            int tile = q >> 1;
            int word = tile & 1;
            int grow = (tile < 2 ? j0 : i0) + rr;
            const __half* src = &g_sp[word][(size_t)(bofs + grow) * DD + kt * 32 + fck * 8];
            uint32_t dst = sbase + buf * BUF_B + tile * TILE_B + rr * (PITCH_H * 2) + fck * 16;
            CP_ASYNC16(dst, src);
        }
    };

    int wm = (wid >> 2) * 64;
    int wn = (wid & 3) * 32;

    float acc[4][4][4];
#pragma unroll
    for (int im = 0; im < 4; im++)
#pragma unroll
        for (int in = 0; in < 4; in++)
#pragma unroll
            for (int q = 0; q < 4; q++) acc[im][in][q] = 0.f;

    fill(0, 0);
    CP_COMMIT();

    int arow = lane & 15;
    int acol = (lane >> 4) * 8;
    int brow = (lane & 7) + ((lane >> 4) << 3);
    int bcol = ((lane >> 3) & 1) * 8;

    for (int kt = 0; kt < 16; kt++) {
        if (kt < 15) { fill((kt + 1) & 1, kt + 1); CP_COMMIT(); }
        if (kt < 15) asm volatile("cp.async.wait_group 1;" ::: "memory");
        else         asm volatile("cp.async.wait_group 0;" ::: "memory");
        __syncthreads();

        uint32_t base = sbase + (kt & 1) * BUF_B;
#pragma unroll
        for (int kc = 0; kc < 2; kc++) {
            int kofs = kc * 16;
            uint32_t ah[4][4], al[4][4];
#pragma unroll
            for (int im = 0; im < 4; im++) {
                uint32_t off = (uint32_t)((wm + im * 16 + arow) * (PITCH_H * 2) + (kofs + acol) * 2);
                LDSM4(ah[im][0], ah[im][1], ah[im][2], ah[im][3], base + 0 * TILE_B + off);
                LDSM4(al[im][0], al[im][1], al[im][2], al[im][3], base + 1 * TILE_B + off);
            }
            uint32_t bh[8], bl[8];
#pragma unroll
            for (int bp = 0; bp < 2; bp++) {
                uint32_t off = (uint32_t)((wn + bp * 16 + brow) * (PITCH_H * 2) + (kofs + bcol) * 2);
                LDSM4(bh[bp*4+0], bh[bp*4+1], bh[bp*4+2], bh[bp*4+3], base + 2 * TILE_B + off);
                LDSM4(bl[bp*4+0], bl[bp*4+1], bl[bp*4+2], bl[bp*4+3], base + 3 * TILE_B + off);
            }
#pragma unroll
            for (int im = 0; im < 4; im++)
#pragma unroll
                for (int in = 0; in < 4; in++) {
                    MMA16816(acc[im][in], ah[im], bh[in*2], bh[in*2+1]);
                    MMA16816(acc[im][in], ah[im], bl[in*2], bl[in*2+1]);
                    MMA16816(acc[im][in], al[im], bh[in*2], bh[in*2+1]);
                }
        }
        __syncthreads();
    }

    float* smemT = (float*)smem;

#pragma unroll
    for (int im = 0; im < 4; im++) {
#pragma unroll
        for (int h2 = 0; h2 < 2; h2++) {
            int row = wm + im * 16 + (lane >> 2) + h2 * 8;
            float xj = xxA[row];
#pragma unroll
            for (int in = 0; in < 4; in++) {
                int n = wn + in * 8 + (lane & 3) * 2;
                float g0 = acc[im][in][h2 * 2 + 0];
                float g1 = acc[im][in][h2 * 2 + 1];
                float v0 = sqrtf(fmaxf((xj + xxB[n])     - 2.0f * g0, 0.0f));
                float v1 = sqrtf(fmaxf((xj + xxB[n + 1]) - 2.0f * g1, 0.0f));
                *(float2*)&g_dist[((size_t)(bofs + j0 + row)) * NN + i0 + n] = make_float2(v0, v1);
                if (!diag) {
                    smemT[(n)     * T_PITCH + row] = v0;
                    smemT[(n + 1) * T_PITCH + row] = v1;
                }
            }
        }
    }

    if (!diag) {
        __syncthreads();
#pragma unroll
        for (int q = 0; q < 16; q++) {
            int fid = tid + 256 * q;
            int nrow = fid >> 5, f4 = fid & 31;
            float4 val = *(float4*)&smemT[nrow * T_PITCH + f4 * 4];
            *(float4*)&g_dist[((size_t)(bofs + i0 + nrow)) * NN + j0 + f4 * 4] = val;
        }
    }
}

// ---------------------------------------------------------------------------
// Kernel 3: top-16 radix select, 4 rows per block, full grid (4096 blocks).
// ---------------------------------------------------------------------------
#define CAND_CAP 512
#define TK_ROWS   0
#define TK_HIST   8192
#define TK_CANDV  9216
#define TK_CANDI  (TK_CANDV + 4 * CAND_CAP)
#define TK_SURE   (TK_CANDI + 4 * CAND_CAP)
#define TK_WIDX   (TK_SURE + 64)
#define TK_SCAL   (TK_WIDX + 64)
#define TK_SMEM_BYTES ((TK_SCAL + 32) * 4)

__device__ __forceinline__ void cmin3(uint32_t& v, uint32_t& i, uint32_t& j,
                                      uint32_t v2, uint32_t i2, uint32_t j2) {
    if (v2 < v || (v2 == v && i2 < i)) { v = v2; i = i2; j = j2; }
}

__global__ __launch_bounds__(256) void topk4_kernel(float* __restrict__ out) {
    extern __shared__ uint32_t sh[];
    uint32_t* rows   = sh + TK_ROWS;
    uint32_t* hist   = sh + TK_HIST;
    uint32_t* candv  = sh + TK_CANDV;
    uint32_t* candi  = sh + TK_CANDI;
    uint32_t* sure   = sh + TK_SURE;
    uint32_t* widx   = sh + TK_WIDX;
    uint32_t* s_b0   = sh + TK_SCAL;
    uint32_t* s_c0   = sh + TK_SCAL + 4;
    uint32_t* s_P    = sh + TK_SCAL + 8;
    uint32_t* s_clt  = sh + TK_SCAL + 12;
    uint32_t* s_nsr  = sh + TK_SCAL + 16;
    uint32_t* s_ncd  = sh + TK_SCAL + 20;

    int tid  = threadIdx.x;
    int lane = tid & 31;
    int wid  = tid >> 5;
    size_t row0 = (size_t)blockIdx.x * 4;

    const uint4* src = (const uint4*)(g_dist + row0 * NN);
#pragma unroll
    for (int q = 0; q < 8; q++)
        ((uint4*)rows)[tid + 256 * q] = src[tid + 256 * q];

#pragma unroll
    for (int q = 0; q < 4; q++) hist[tid + 256 * q] = 0;
    if (tid < 4) { s_nsr[tid] = 0; s_ncd[tid] = 0; }
    __syncthreads();

    // ---- level 0 hist: bits [31:24], warp-aggregated ----
#pragma unroll
    for (int r = 0; r < 4; r++) {
        const uint32_t* rw = rows + r * NN + tid * 8;
#pragma unroll
        for (int q = 0; q < 8; q++) {
            uint32_t bin = rw[q] >> 24;
            uint32_t mask = __match_any_sync(0xffffffffu, bin);
            if (lane == (__ffs(mask) - 1)) atomicAdd(&hist[r * 256 + bin], __popc(mask));
        }
    }
    __syncthreads();

    if (wid < 4) {
        int r = wid;
        uint32_t loc[8], s = 0;
#pragma unroll
        for (int i = 0; i < 8; i++) { loc[i] = hist[r * 256 + lane * 8 + i]; s += loc[i]; }
        uint32_t incl = s;
#pragma unroll
        for (int off = 1; off < 32; off <<= 1) {
            uint32_t t2 = __shfl_up_sync(0xffffffffu, incl, off);
            if (lane >= off) incl += t2;
        }
        uint32_t run = incl - s;
#pragma unroll
        for (int i = 0; i < 8; i++) {
            if (run < 16u && 16u <= run + loc[i]) { s_b0[r] = lane * 8 + i; s_c0[r] = run; }
            run += loc[i];
        }
    }
    __syncthreads();

    uint32_t b0r[4];
#pragma unroll
    for (int r = 0; r < 4; r++) b0r[r] = s_b0[r];

#pragma unroll
    for (int q = 0; q < 4; q++) hist[tid + 256 * q] = 0;
    __syncthreads();

    // ---- level 1 hist: bits [23:16] where top byte == b0 ----
#pragma unroll
    for (int r = 0; r < 4; r++) {
        const uint32_t* rw = rows + r * NN + tid * 8;
        uint32_t b0 = b0r[r];
#pragma unroll
        for (int q = 0; q < 8; q++) {
            uint32_t v = rw[q];
            bool act = ((v >> 24) == b0);
            uint32_t bin = act ? ((v >> 16) & 255u) : (256u + lane);
            uint32_t mask = __match_any_sync(0xffffffffu, bin);
            if (act && lane == (__ffs(mask) - 1)) atomicAdd(&hist[r * 256 + bin], __popc(mask));
        }
    }
    __syncthreads();

    if (wid < 4) {
        int r = wid;
        uint32_t k1 = 16u - s_c0[r];
        uint32_t loc[8], s = 0;
#pragma unroll
        for (int i = 0; i < 8; i++) { loc[i] = hist[r * 256 + lane * 8 + i]; s += loc[i]; }
        uint32_t incl = s;
#pragma unroll
        for (int off = 1; off < 32; off <<= 1) {
            uint32_t t2 = __shfl_up_sync(0xffffffffu, incl, off);
            if (lane >= off) incl += t2;
        }
        uint32_t run = incl - s;
#pragma unroll
        for (int i = 0; i < 8; i++) {
            if (run < k1 && k1 <= run + loc[i]) {
                s_P[r]   = (s_b0[r] << 8) | (uint32_t)(lane * 8 + i);
                s_clt[r] = s_c0[r] + run;
            }
            run += loc[i];
        }
    }
    __syncthreads();

    // ---- gather sure / candidate per row ----
#pragma unroll
    for (int r = 0; r < 4; r++) {
        uint32_t P = s_P[r];
        const uint32_t* rw = rows + r * NN + tid * 8;
#pragma unroll
        for (int q = 0; q < 8; q++) {
            uint32_t v = rw[q];
            uint32_t hi = v >> 16;
            if (hi < P) {
                uint32_t p = atomicAdd(&s_nsr[r], 1u);
                sure[r * 16 + p] = tid * 8 + q;
            } else if (hi == P) {
                uint32_t p = atomicAdd(&s_ncd[r], 1u);
                if (p < CAND_CAP) {
                    candv[r * CAND_CAP + p] = v;
                    candi[r * CAND_CAP + p] = tid * 8 + q;
                }
            }
        }
    }
    __syncthreads();

    // ---- warp r: stable-min rounds over its candidate list ----
    if (wid < 4) {
        int r = wid;
        uint32_t m = 16u - s_clt[r];
        uint32_t n = min(s_ncd[r], (uint32_t)CAND_CAP);
        uint32_t* cv = candv + r * CAND_CAP;
        uint32_t* ci = candi + r * CAND_CAP;
        for (uint32_t it = 0; it < m; it++) {
            uint32_t bv = 0xffffffffu, bi = 0xffffffffu, bj = 0xffffffffu;
            for (uint32_t j = lane; j < n; j += 32)
                cmin3(bv, bi, bj, cv[j], ci[j], j);
#pragma unroll
            for (int off = 16; off; off >>= 1) {
                uint32_t ov = __shfl_down_sync(0xffffffffu, bv, off);
                uint32_t oi = __shfl_down_sync(0xffffffffu, bi, off);
                uint32_t oj = __shfl_down_sync(0xffffffffu, bj, off);
                cmin3(bv, bi, bj, ov, oi, oj);
            }
            if (lane == 0) {
                widx[r * 16 + it] = bi;
                cv[bj] = 0xffffffffu;
                ci[bj] = 0xffffffffu;
            }
            __syncwarp();
        }
    }
    __syncthreads();

    // ---- write: zero 4 rows, then scatter ones (warp r handles row r) ----
    float* orow0 = out + row0 * NN;
    float4 z = make_float4(0.f, 0.f, 0.f, 0.f);
#pragma unroll
    for (int q = 0; q < 8; q++)
        ((float4*)orow0)[tid + 256 * q] = z;
    __syncthreads();
    if (wid < 4) {
        int r = wid;
        uint32_t clt = s_clt[r], m = 16u - clt;
        float* orow = orow0 + (size_t)r * NN;
        if (lane < clt)                   orow[sure[r * 16 + lane]] = 1.0f;
        if (lane >= 16 && lane < 16 + m)  orow[widx[r * 16 + lane - 16]] = 1.0f;
    }
}

// ---------------------------------------------------------------------------
extern "C" void kernel_launch(void* const* d_in, const int* in_sizes, int n_in,
                              void* d_out, int out_size) {
    const float* put = (const float*)d_in[0];
    float* out = (float*)d_out;

    cudaFuncSetAttribute(dist_mma_kernel, cudaFuncAttributeMaxDynamicSharedMemorySize, SM_TOTAL);
    cudaFuncSetAttribute(topk4_kernel, cudaFuncAttributeMaxDynamicSharedMemorySize, TK_SMEM_BYTES);

    split_kernel<<<(BB * NN * DD) / (256 * 4), 256>>>(put);
    xx_kernel<<<(BB * NN) / 8, 256>>>(put);
    dist_mma_kernel<<<dim3(16, 16, BB), 256, SM_TOTAL>>>();
    topk4_kernel<<<(BB * NN) / 4, 256, TK_SMEM_BYTES>>>(out);
}